// round 13
// baseline (speedup 1.0000x reference)
#include <cuda_runtime.h>
#include <cuda_fp16.h>
#include <cstdint>

#define K_DIM 4096
#define N_DIM 4096
#define M_MAX 8192

#define BM 128
#define BN 128
#define BKE 64                 // K elements per stage (128 bytes fp16)
#define A_BYTES 16384          // 128 rows * 128B
#define B_BYTES 16384          // 128 rows * 128B
#define STAGE_BYTES (A_BYTES + B_BYTES)   // 32KB
#define STAGES 3               // 96KB per CTA -> 2 CTAs/SM

// Scratch (allocation-free rule: __device__ globals)
__device__ __half g_Xh[(size_t)M_MAX * K_DIM];
__device__ __half g_Wh[(size_t)N_DIM * K_DIM];

// ---------------- helpers ----------------
static __device__ __forceinline__ uint32_t smem_u32(const void* p) {
    return (uint32_t)__cvta_generic_to_shared(p);
}

static __device__ __forceinline__ void cp_async16(uint32_t dst, const void* src) {
    asm volatile("cp.async.cg.shared.global [%0], [%1], 16;\n"
                 :: "r"(dst), "l"(__cvta_generic_to_global(src)));
}

static __device__ __forceinline__ void ldsm4(uint32_t* r, uint32_t addr) {
    asm volatile("ldmatrix.sync.aligned.m8n8.x4.shared.b16 {%0,%1,%2,%3}, [%4];\n"
                 : "=r"(r[0]), "=r"(r[1]), "=r"(r[2]), "=r"(r[3])
                 : "r"(addr));
}

static __device__ __forceinline__ void mma16816(float* c, const uint32_t* a,
                                                uint32_t b0, uint32_t b1) {
    asm volatile(
        "mma.sync.aligned.m16n8k16.row.col.f32.f16.f16.f32 "
        "{%0,%1,%2,%3}, {%4,%5,%6,%7}, {%8,%9}, {%0,%1,%2,%3};\n"
        : "+f"(c[0]), "+f"(c[1]), "+f"(c[2]), "+f"(c[3])
        : "r"(a[0]), "r"(a[1]), "r"(a[2]), "r"(a[3]), "r"(b0), "r"(b1));
}

// ------- merged prep kernel: split x -> fp16  AND  Wh = fp16(W + U*s*V^T) -----
__global__ void prep_kernel(const float* __restrict__ x,
                            const float* __restrict__ W,
                            const float* __restrict__ U,
                            const float* __restrict__ S,
                            const float* __restrict__ V,
                            int nSplit, int n4) {
    if ((int)blockIdx.x < nSplit) {
        int i = blockIdx.x * blockDim.x + threadIdx.x;
        if (i >= n4) return;
        float4 v = reinterpret_cast<const float4*>(x)[i];
        float f[4] = {v.x, v.y, v.z, v.w};
        union P4 { __half h[4]; uint2 u; } ph;
#pragma unroll
        for (int j = 0; j < 4; j++) ph.h[j] = __float2half(f[j]);
        reinterpret_cast<uint2*>(g_Xh)[i] = ph.u;
        return;
    }
    __shared__ float sV[256][17];
    __shared__ float sUs[16][16];
    int bid = blockIdx.x - nSplit;
    int nb = bid >> 4;
    int kb = bid & 15;
    int n0 = nb * 16, k0 = kb * 256;
    int tid = threadIdx.x;
#pragma unroll 4
    for (int r = 0; r < 16; r++)
        sV[tid][r] = V[(size_t)(k0 + tid) * 16 + r];
    if (tid < 16 * 16) {
        int nn = tid >> 4, r = tid & 15;
        sUs[nn][r] = U[(size_t)(n0 + nn) * 16 + r] * S[r];
    }
    __syncthreads();
    int k = k0 + tid;
#pragma unroll 4
    for (int nn = 0; nn < 16; nn++) {
        int n = n0 + nn;
        float acc = W[(size_t)n * K_DIM + k];
#pragma unroll
        for (int r = 0; r < 16; r++) acc += sUs[nn][r] * sV[tid][r];
        g_Wh[(size_t)n * K_DIM + k] = __float2half(acc);
    }
}

// ---------------- GEMM: out = Xh @ Wh^T ----------------
// 128x128 CTA tile, 256 threads (8 warps 2x4, warp tile 64x32), BK=64,
// cp.async 3-stage depth-2 prefetch, one barrier/stage, 2 CTAs/SM
// -> 4 warp streams per SMSP from 2 independent CTAs.
__global__ __launch_bounds__(256, 2)
void gemm_kernel(float* __restrict__ C) {
    extern __shared__ char smem[];
    const int tid  = threadIdx.x;
    const int lane = tid & 31;
    const int wid  = tid >> 5;
    const int m0 = blockIdx.y * BM;
    const int n0 = blockIdx.x * BN;
    const int warpM = (wid >> 2) * 64;   // 2 M groups
    const int warpN = (wid & 3) * 32;    // 4 N groups

    const uint32_t sbase = smem_u32(smem);

    // per-thread cp.async geometry: 8 chunks of 16B per stage
    const int lrow = tid >> 3;                      // 0..31
    const int lc   = tid & 7;                       // 16B chunk within 128B row
    const uint32_t scol = (uint32_t)((lc ^ (lrow & 7)) << 4);  // swizzled

    const __half* gX = g_Xh + (size_t)m0 * K_DIM;
    const __half* gW = g_Wh + (size_t)n0 * K_DIM;

    float acc[4][4][4];
#pragma unroll
    for (int a = 0; a < 4; a++)
#pragma unroll
        for (int b = 0; b < 4; b++)
#pragma unroll
            for (int d = 0; d < 4; d++) acc[a][b][d] = 0.f;

    const int nT = K_DIM / BKE;  // 64

    auto load_tile = [&](int t) {
        if (t < nT) {
            uint32_t s0 = sbase + (uint32_t)(t % STAGES) * STAGE_BYTES;
            size_t gk = (size_t)t * BKE + (size_t)lc * 8;
#pragma unroll
            for (int i = 0; i < 4; i++) {           // A: 128 rows
                int row = lrow + i * 32;
                cp_async16(s0 + (uint32_t)row * 128 + scol,
                           gX + (size_t)row * K_DIM + gk);
            }
#pragma unroll
            for (int i = 0; i < 4; i++) {           // B: 128 rows
                int row = lrow + i * 32;
                cp_async16(s0 + A_BYTES + (uint32_t)row * 128 + scol,
                           gW + (size_t)row * K_DIM + gk);
            }
        }
        asm volatile("cp.async.commit_group;\n");   // empty group ok past end
    };

    auto compute = [&](int stage) {
        uint32_t sA = sbase + (uint32_t)stage * STAGE_BYTES;
        uint32_t sB = sA + A_BYTES;
#pragma unroll
        for (int kk = 0; kk < 4; kk++) {
            uint32_t a[4][4], b[2][4];
#pragma unroll
            for (int mt = 0; mt < 4; mt++) {
                int r = warpM + mt * 16 + (lane & 15);
                int c = kk * 2 + (lane >> 4);
                uint32_t off = (uint32_t)r * 128 + (uint32_t)((c ^ (r & 7)) << 4);
                ldsm4(a[mt], sA + off);
            }
#pragma unroll
            for (int bt = 0; bt < 2; bt++) {
                int r = warpN + bt * 16 + (lane & 7) + ((lane >> 4) << 3);
                int c = kk * 2 + ((lane >> 3) & 1);
                uint32_t off = (uint32_t)r * 128 + (uint32_t)((c ^ (r & 7)) << 4);
                ldsm4(b[bt], sB + off);
            }
#pragma unroll
            for (int mt = 0; mt < 4; mt++)
#pragma unroll
                for (int bt = 0; bt < 2; bt++) {
                    mma16816(acc[mt][2 * bt],     a[mt], b[bt][0], b[bt][1]);
                    mma16816(acc[mt][2 * bt + 1], a[mt], b[bt][2], b[bt][3]);
                }
        }
    };

    load_tile(0);
    load_tile(1);

    for (int t = 0; t < nT; t++) {
        // FIFO group retirement: <=1 pending  =>  group t retired
        asm volatile("cp.async.wait_group 1;\n" ::: "memory");
        __syncthreads();          // all warps done with compute(t-1); stage t visible
        load_tile(t + 2);         // writes slot (t+2)%3 — disjoint from t, t+1
        compute(t % STAGES);
    }

    // epilogue: fp32 stores, float2 per quad half
#pragma unroll
    for (int mt = 0; mt < 4; mt++) {
        int r = m0 + warpM + mt * 16 + (lane >> 2);
#pragma unroll
        for (int nt = 0; nt < 4; nt++) {
            int c = n0 + warpN + nt * 8 + (lane & 3) * 2;
            *reinterpret_cast<float2*>(&C[(size_t)r * N_DIM + c]) =
                make_float2(acc[mt][nt][0], acc[mt][nt][1]);
            *reinterpret_cast<float2*>(&C[(size_t)(r + 8) * N_DIM + c]) =
                make_float2(acc[mt][nt][2], acc[mt][nt][3]);
        }
    }
}

// ---------------- launch ----------------
extern "C" void kernel_launch(void* const* d_in, const int* in_sizes, int n_in,
                              void* d_out, int out_size) {
    const float* x = (const float*)d_in[0];
    const float* W = (const float*)d_in[1];
    const float* U = (const float*)d_in[2];
    const float* S = (const float*)d_in[3];
    const float* V = (const float*)d_in[4];
    float* out = (float*)d_out;

    int M = in_sizes[0] / K_DIM;  // 8192

    cudaFuncSetAttribute(gemm_kernel, cudaFuncAttributeMaxDynamicSharedMemorySize,
                         STAGES * STAGE_BYTES);

    int n4 = (M * K_DIM) / 4;
    int nSplit = (n4 + 255) / 256;
    int nAdapt = (N_DIM / 16) * (K_DIM / 256);   // 4096
    prep_kernel<<<nSplit + nAdapt, 256>>>(x, W, U, S, V, nSplit, n4);
    gemm_kernel<<<dim3(N_DIM / BN, M / BM), 256, STAGES * STAGE_BYTES>>>(out);
}

// round 16
// speedup vs baseline: 1.1022x; 1.1022x over previous
#include <cuda_runtime.h>
#include <cuda_fp16.h>
#include <cstdint>

#define K_DIM 4096
#define N_DIM 4096
#define M_MAX 8192

#define BM 128
#define BN 128
#define BKE 64                 // K elements per stage (128 bytes fp16)
#define A_BYTES 16384          // 128 rows * 128B
#define B_BYTES 16384          // 128 rows * 128B
#define STAGE_BYTES (A_BYTES + B_BYTES)   // 32KB
#define STAGES 3               // 96KB per CTA -> 2 CTAs/SM

// Scratch (allocation-free rule: __device__ globals)
__device__ __half g_Xh[(size_t)M_MAX * K_DIM];
__device__ __half g_Wh[(size_t)N_DIM * K_DIM];

// ---------------- helpers ----------------
static __device__ __forceinline__ uint32_t smem_u32(const void* p) {
    return (uint32_t)__cvta_generic_to_shared(p);
}

static __device__ __forceinline__ void cp_async16(uint32_t dst, const void* src) {
    asm volatile("cp.async.cg.shared.global [%0], [%1], 16;\n"
                 :: "r"(dst), "l"(__cvta_generic_to_global(src)));
}

static __device__ __forceinline__ void ldsm4(uint32_t* r, uint32_t addr) {
    asm volatile("ldmatrix.sync.aligned.m8n8.x4.shared.b16 {%0,%1,%2,%3}, [%4];\n"
                 : "=r"(r[0]), "=r"(r[1]), "=r"(r[2]), "=r"(r[3])
                 : "r"(addr));
}

static __device__ __forceinline__ void mma16816(float* c, const uint32_t* a,
                                                uint32_t b0, uint32_t b1) {
    asm volatile(
        "mma.sync.aligned.m16n8k16.row.col.f32.f16.f16.f32 "
        "{%0,%1,%2,%3}, {%4,%5,%6,%7}, {%8,%9}, {%0,%1,%2,%3};\n"
        : "+f"(c[0]), "+f"(c[1]), "+f"(c[2]), "+f"(c[3])
        : "r"(a[0]), "r"(a[1]), "r"(a[2]), "r"(a[3]), "r"(b0), "r"(b1));
}

// ------- merged prep kernel -------
// Blocks [0, nSplit): x -> fp16, 8 floats/thread, 16B stores.
// Blocks [nSplit, +2048): Wh = fp16(W + U*s*V^T), 2 k/thread, __half2 stores.
__global__ void prep_kernel(const float* __restrict__ x,
                            const float* __restrict__ W,
                            const float* __restrict__ U,
                            const float* __restrict__ S,
                            const float* __restrict__ V,
                            int nSplit, int n8) {
    if ((int)blockIdx.x < nSplit) {
        int i = blockIdx.x * blockDim.x + threadIdx.x;
        if (i >= n8) return;
        const float4* x4 = reinterpret_cast<const float4*>(x);
        float4 v0 = x4[2 * i];
        float4 v1 = x4[2 * i + 1];
        float f[8] = {v0.x, v0.y, v0.z, v0.w, v1.x, v1.y, v1.z, v1.w};
        union P8 { __half h[8]; uint4 u; } ph;
#pragma unroll
        for (int j = 0; j < 8; j++) ph.h[j] = __float2half(f[j]);
        reinterpret_cast<uint4*>(g_Xh)[i] = ph.u;
        return;
    }
    // adapt: block = 16 n-rows x 512 k-cols; thread owns 2 consecutive k.
    __shared__ float sV[512][17];
    __shared__ float sUs[16][16];
    int bid = blockIdx.x - nSplit;
    int nb = bid >> 3;           // 0..255
    int kb = bid & 7;            // 0..7
    int n0 = nb * 16, k0 = kb * 512;
    int tid = threadIdx.x;
#pragma unroll
    for (int rr = 0; rr < 2; rr++) {
        int row = tid * 2 + rr;
#pragma unroll
        for (int r = 0; r < 16; r++)
            sV[row][r] = V[(size_t)(k0 + row) * 16 + r];
    }
    if (tid < 16 * 16) {
        int nn = tid >> 4, r = tid & 15;
        sUs[nn][r] = U[(size_t)(n0 + nn) * 16 + r] * S[r];
    }
    __syncthreads();
    int k = k0 + tid * 2;
#pragma unroll 2
    for (int nn = 0; nn < 16; nn++) {
        int n = n0 + nn;
        float2 w = *reinterpret_cast<const float2*>(&W[(size_t)n * K_DIM + k]);
        float a0 = w.x, a1 = w.y;
#pragma unroll
        for (int r = 0; r < 16; r++) {
            float us = sUs[nn][r];
            a0 += us * sV[tid * 2][r];
            a1 += us * sV[tid * 2 + 1][r];
        }
        *reinterpret_cast<__half2*>(&g_Wh[(size_t)n * K_DIM + k]) =
            __floats2half2_rn(a0, a1);
    }
}

// ---------------- GEMM: out = Xh @ Wh^T ----------------
// 128x128 CTA tile, 128 threads (4 warps, 64x64 warp tiles), BK=64,
// cp.async 3-stage, 2 CTAs/SM. Stage head reordered: ldmatrix kk0 BEFORE
// the cp.async burst so the tensor pipe is fed across the stage boundary.
__global__ __launch_bounds__(128, 2)
void gemm_kernel(float* __restrict__ C) {
    extern __shared__ char smem[];
    const int tid  = threadIdx.x;
    const int lane = tid & 31;
    const int wid  = tid >> 5;
    const int m0 = blockIdx.y * BM;
    const int n0 = blockIdx.x * BN;
    const int warpM = (wid >> 1) * 64;
    const int warpN = (wid & 1) * 64;

    const uint32_t sbase = smem_u32(smem);

    // per-thread cp.async geometry: 16 chunks of 16B per stage
    const int lrow = tid >> 3;                      // 0..15
    const int lc   = tid & 7;                       // 16B chunk within 128B row
    const uint32_t scol = (uint32_t)((lc ^ (lrow & 7)) << 4);  // swizzled

    const __half* gX = g_Xh + (size_t)m0 * K_DIM;
    const __half* gW = g_Wh + (size_t)n0 * K_DIM;

    float acc[4][8][4];
#pragma unroll
    for (int a = 0; a < 4; a++)
#pragma unroll
        for (int b = 0; b < 8; b++)
#pragma unroll
            for (int d = 0; d < 4; d++) acc[a][b][d] = 0.f;

    const int nT = K_DIM / BKE;  // 64

    auto load_tile = [&](int t) {
        if (t < nT) {
            uint32_t s0 = sbase + (uint32_t)(t % STAGES) * STAGE_BYTES;
            size_t gk = (size_t)t * BKE + (size_t)lc * 8;
#pragma unroll
            for (int i = 0; i < 8; i++) {           // A: 128 rows
                int row = lrow + i * 16;
                cp_async16(s0 + (uint32_t)row * 128 + scol,
                           gX + (size_t)row * K_DIM + gk);
            }
#pragma unroll
            for (int i = 0; i < 8; i++) {           // B: 128 rows
                int row = lrow + i * 16;
                cp_async16(s0 + A_BYTES + (uint32_t)row * 128 + scol,
                           gW + (size_t)row * K_DIM + gk);
            }
        }
        asm volatile("cp.async.commit_group;\n");   // empty group ok past end
    };

    // fragment double-buffers
    uint32_t afrag[2][4][4], bfrag[2][4][4];

    auto load_frags = [&](uint32_t sA, uint32_t sB, int kk, int buf) {
#pragma unroll
        for (int mt = 0; mt < 4; mt++) {
            int r = warpM + mt * 16 + (lane & 15);
            int c = kk * 2 + (lane >> 4);
            uint32_t off = (uint32_t)r * 128 + (uint32_t)((c ^ (r & 7)) << 4);
            ldsm4(afrag[buf][mt], sA + off);
        }
#pragma unroll
        for (int bt = 0; bt < 4; bt++) {
            int r = warpN + bt * 16 + (lane & 7) + ((lane >> 4) << 3);
            int c = kk * 2 + ((lane >> 3) & 1);
            uint32_t off = (uint32_t)r * 128 + (uint32_t)((c ^ (r & 7)) << 4);
            ldsm4(bfrag[buf][bt], sB + off);
        }
    };

    auto mma_block = [&](int cur) {
#pragma unroll
        for (int mt = 0; mt < 4; mt++)
#pragma unroll
            for (int bt = 0; bt < 4; bt++) {
                mma16816(acc[mt][2 * bt],     afrag[cur][mt],
                         bfrag[cur][bt][0], bfrag[cur][bt][1]);
                mma16816(acc[mt][2 * bt + 1], afrag[cur][mt],
                         bfrag[cur][bt][2], bfrag[cur][bt][3]);
            }
    };

    load_tile(0);
    load_tile(1);

    for (int t = 0; t < nT; t++) {
        // FIFO group retirement: <=1 pending  =>  group t retired
        asm volatile("cp.async.wait_group 1;\n" ::: "memory");
        __syncthreads();          // all warps done with compute(t-1); stage t visible

        uint32_t sA = sbase + (uint32_t)(t % STAGES) * STAGE_BYTES;
        uint32_t sB = sA + A_BYTES;

        load_frags(sA, sB, 0, 0);   // feed tensor pipe FIRST
        load_tile(t + 2);           // cp.async burst hides under kk0 HMMAs
#pragma unroll
        for (int kk = 0; kk < 4; kk++) {
            const int cur = kk & 1;
            if (kk < 3) load_frags(sA, sB, kk + 1, cur ^ 1);  // prefetch next kk
            mma_block(cur);
        }
    }

    // epilogue: fp32 stores, float2 per quad half
#pragma unroll
    for (int mt = 0; mt < 4; mt++) {
        int r = m0 + warpM + mt * 16 + (lane >> 2);
#pragma unroll
        for (int nt = 0; nt < 8; nt++) {
            int c = n0 + warpN + nt * 8 + (lane & 3) * 2;
            *reinterpret_cast<float2*>(&C[(size_t)r * N_DIM + c]) =
                make_float2(acc[mt][nt][0], acc[mt][nt][1]);
            *reinterpret_cast<float2*>(&C[(size_t)(r + 8) * N_DIM + c]) =
                make_float2(acc[mt][nt][2], acc[mt][nt][3]);
        }
    }
}

// ---------------- launch ----------------
extern "C" void kernel_launch(void* const* d_in, const int* in_sizes, int n_in,
                              void* d_out, int out_size) {
    const float* x = (const float*)d_in[0];
    const float* W = (const float*)d_in[1];
    const float* U = (const float*)d_in[2];
    const float* S = (const float*)d_in[3];
    const float* V = (const float*)d_in[4];
    float* out = (float*)d_out;

    int M = in_sizes[0] / K_DIM;  // 8192

    cudaFuncSetAttribute(gemm_kernel, cudaFuncAttributeMaxDynamicSharedMemorySize,
                         STAGES * STAGE_BYTES);

    int n8 = (M * K_DIM) / 8;
    int nSplit = (n8 + 255) / 256;                 // 16384
    int nAdapt = (N_DIM / 16) * (K_DIM / 512);     // 2048
    prep_kernel<<<nSplit + nAdapt, 256>>>(x, W, U, S, V, nSplit, n8);
    gemm_kernel<<<dim3(N_DIM / BN, M / BM), 128, STAGES * STAGE_BYTES>>>(out);
}